// round 2
// baseline (speedup 1.0000x reference)
#include <cuda_runtime.h>

#define BB 2
#define LL 512
#define DD 256
#define NN 256
#define DT 64
#define PW 576   // DT + 2*DD

// scratch (device globals — no allocations allowed)
__device__ float g_proj[BB * LL * PW];      // [row, 576] : dt_raw | beta | gamma
__device__ float g_dt  [BB * LL * DD];
__device__ float g_dtx [BB * LL * DD];
__device__ float g_xd  [BB * LL * DD];
__device__ float g_A2  [DD * NN];           // -exp(alpha_log) * log2(e)

__device__ __forceinline__ float ex2_approx(float x) {
    float r;
    asm("ex2.approx.ftz.f32 %0, %1;" : "=f"(r) : "f"(x));
    return r;
}

// ---------------------------------------------------------------------------
// Kernel 0: A2[d][n] = -exp(alpha_log[d][n]) * log2(e)
// ---------------------------------------------------------------------------
__global__ void a2_kernel(const float* __restrict__ alog) {
    int i = blockIdx.x * blockDim.x + threadIdx.x;
    if (i < DD * NN)
        g_A2[i] = -__expf(alog[i]) * 1.4426950408889634f;
}

// ---------------------------------------------------------------------------
// Kernel 1: proj = x @ W_in   ([1024,256] x [256,576] -> [1024,576])
// ---------------------------------------------------------------------------
__global__ void proj_kernel(const float* __restrict__ x, const float* __restrict__ W) {
    __shared__ float xs[32][33];
    __shared__ float ws[32][33];
    int row = blockIdx.y * 32 + threadIdx.y;
    int col = blockIdx.x * 32 + threadIdx.x;
    float acc = 0.f;
    for (int kt = 0; kt < DD; kt += 32) {
        xs[threadIdx.y][threadIdx.x] = x[row * DD + kt + threadIdx.x];
        ws[threadIdx.y][threadIdx.x] = W[(kt + threadIdx.y) * PW + col];
        __syncthreads();
#pragma unroll
        for (int k = 0; k < 32; k++)
            acc = fmaf(xs[threadIdx.y][k], ws[k][threadIdx.x], acc);
        __syncthreads();
    }
    g_proj[row * PW + col] = acc;
}

// ---------------------------------------------------------------------------
// Kernel 2: dt = softplus(proj[:, :64] @ W_dt + b_dt); dtx = dt*x; xd = x*delta
// ---------------------------------------------------------------------------
__global__ void dt_kernel(const float* __restrict__ x, const float* __restrict__ Wdt,
                          const float* __restrict__ bdt, const float* __restrict__ delta) {
    int r = blockIdx.x;
    int d = threadIdx.x;
    __shared__ float sp[DT];
    if (d < DT) sp[d] = g_proj[r * PW + d];
    __syncthreads();
    float acc = bdt[d];
#pragma unroll
    for (int k = 0; k < DT; k++)
        acc = fmaf(sp[k], Wdt[k * DD + d], acc);
    float dt = fmaxf(acc, 0.f) + log1pf(__expf(-fabsf(acc)));
    float xv = x[r * DD + d];
    int idx = r * DD + d;
    g_dt[idx]  = dt;
    g_dtx[idx] = dt * xv;
    g_xd[idx]  = xv * delta[d];
}

// ---------------------------------------------------------------------------
// Kernel 3: sequential scan. One warp per (b, d); lane owns 8 consecutive n.
// 8-step batching: xd prefetched per batch; y-reduction done as a single
// transposed multi-value butterfly (9 SHFLs per 8 steps).
// ---------------------------------------------------------------------------
__global__ void __launch_bounds__(128) scan_kernel(float* __restrict__ out) {
    const int warp = threadIdx.x >> 5;
    const int lane = threadIdx.x & 31;
    const int b = blockIdx.x >> 6;                 // 64 CTAs per batch index
    const int d = ((blockIdx.x & 63) << 2) + warp; // 4 d per CTA
    const int nb = lane * 8;

    float a2[8], st[8];
#pragma unroll
    for (int j = 0; j < 8; j++) {
        a2[j] = g_A2[d * NN + nb + j];
        st[j] = 0.f;
    }

    const float* projbase = g_proj + (size_t)b * LL * PW;
    const float* dtp  = g_dt  + (size_t)b * LL * DD + d;
    const float* dtxp = g_dtx + (size_t)b * LL * DD + d;
    const float* xdp  = g_xd  + (size_t)b * LL * DD + d;
    float* outp = out + (size_t)b * LL * DD + d;

    // prefetch step 0
    float4 be0, be1, ga0, ga1;
    float dt, dtx;
    {
        const float* pr = projbase;
        be0 = *(const float4*)(pr + DT + nb);
        be1 = *(const float4*)(pr + DT + nb + 4);
        ga0 = *(const float4*)(pr + DT + DD + nb);
        ga1 = *(const float4*)(pr + DT + DD + nb + 4);
        dt  = dtp[0];
        dtx = dtxp[0];
    }

    const unsigned fm = 0xffffffffu;
    const int bt0 = lane & 1;
    const int bt1 = (lane >> 1) & 1;
    const int bt2 = (lane >> 2) & 1;

    for (int lb = 0; lb < LL; lb += 8) {
        // batch prefetch: xd for the 8 outputs of this batch (lanes 0-7)
        float xdv = 0.f;
        if (lane < 8) xdv = xdp[(lb + lane) * DD];

        float yl[8];
#pragma unroll
        for (int k = 0; k < 8; k++) {
            int l = lb + k;
            int ln = (l + 1 < LL) ? (l + 1) : l;   // clamp (last value unused)
            const float* pr = projbase + ln * PW;
            float4 nbe0 = *(const float4*)(pr + DT + nb);
            float4 nbe1 = *(const float4*)(pr + DT + nb + 4);
            float4 nga0 = *(const float4*)(pr + DT + DD + nb);
            float4 nga1 = *(const float4*)(pr + DT + DD + nb + 4);
            float ndt  = dtp[ln * DD];
            float ndtx = dtxp[ln * DD];

            float be[8] = {be0.x, be0.y, be0.z, be0.w, be1.x, be1.y, be1.z, be1.w};
            float ga[8] = {ga0.x, ga0.y, ga0.z, ga0.w, ga1.x, ga1.y, ga1.z, ga1.w};

            float acc0 = 0.f, acc1 = 0.f, acc2 = 0.f, acc3 = 0.f;
#pragma unroll
            for (int j = 0; j < 8; j++) {
                float a  = ex2_approx(dt * a2[j]);     // exp(dt*alpha)
                st[j] = fmaf(a, st[j], dtx * be[j]);
                float p = st[j] * ga[j];
                if ((j & 3) == 0) acc0 += p;
                else if ((j & 3) == 1) acc1 += p;
                else if ((j & 3) == 2) acc2 += p;
                else acc3 += p;
            }
            yl[k] = (acc0 + acc1) + (acc2 + acc3);

            be0 = nbe0; be1 = nbe1; ga0 = nga0; ga1 = nga1;
            dt = ndt; dtx = ndtx;
        }

        // transposed multi-value reduction: Y[k] = sum over lanes of yl[k],
        // ending with Y[lane & 7] in every lane.  9 SHFLs total.
        // round 0: lane bit0 <-> value bit0
        float s, r0, r1, r2, r3;
        s = bt0 ? yl[0] : yl[1];
        r0 = (bt0 ? yl[1] : yl[0]) + __shfl_xor_sync(fm, s, 1);
        s = bt0 ? yl[2] : yl[3];
        r1 = (bt0 ? yl[3] : yl[2]) + __shfl_xor_sync(fm, s, 1);
        s = bt0 ? yl[4] : yl[5];
        r2 = (bt0 ? yl[5] : yl[4]) + __shfl_xor_sync(fm, s, 1);
        s = bt0 ? yl[6] : yl[7];
        r3 = (bt0 ? yl[7] : yl[6]) + __shfl_xor_sync(fm, s, 1);
        // round 1: lane bit1 <-> value bit1
        float q0, q1;
        s = bt1 ? r0 : r1;
        q0 = (bt1 ? r1 : r0) + __shfl_xor_sync(fm, s, 2);
        s = bt1 ? r2 : r3;
        q1 = (bt1 ? r3 : r2) + __shfl_xor_sync(fm, s, 2);
        // round 2: lane bit2 <-> value bit2
        float v;
        s = bt2 ? q0 : q1;
        v = (bt2 ? q1 : q0) + __shfl_xor_sync(fm, s, 4);
        // rounds 3,4: plain butterfly over remaining lane bits
        v += __shfl_xor_sync(fm, v, 8);
        v += __shfl_xor_sync(fm, v, 16);
        // lane k now holds Y[k] (k = lane&7); lanes 0-7 store this batch
        if (lane < 8)
            outp[(lb + lane) * DD] = v + xdv;
    }
}

// ---------------------------------------------------------------------------
extern "C" void kernel_launch(void* const* d_in, const int* in_sizes, int n_in,
                              void* d_out, int out_size) {
    const float* x      = (const float*)d_in[0];  // [2,512,256]
    const float* W_in   = (const float*)d_in[1];  // [256,576]
    const float* W_dt   = (const float*)d_in[2];  // [64,256]
    const float* b_dt   = (const float*)d_in[3];  // [256]
    const float* alog   = (const float*)d_in[4];  // [256,256]
    const float* delta  = (const float*)d_in[5];  // [256]
    float* out = (float*)d_out;                   // [2,512,256]

    a2_kernel<<<(DD * NN + 255) / 256, 256>>>(alog);

    dim3 pgrid(PW / 32, (BB * LL) / 32);
    dim3 pblk(32, 32);
    proj_kernel<<<pgrid, pblk>>>(x, W_in);

    dt_kernel<<<BB * LL, DD>>>(x, W_dt, b_dt, delta);

    scan_kernel<<<BB * 64, 128>>>(out);
}

// round 3
// speedup vs baseline: 2.3865x; 2.3865x over previous
#include <cuda_runtime.h>

#define BB 2
#define LL 512
#define DD 256
#define NN 256
#define DT 64
#define PW 576   // DT + 2*DD

// scratch (device globals — no allocations allowed); +8 rows of padding so the
// software pipeline can over-prefetch past the end without bounds checks.
__device__ float g_proj[(BB * LL + 8) * PW];   // [row, 576] : dt_raw | beta | gamma
__device__ float g_dt  [(BB * LL + 8) * DD];
__device__ float g_dtx [(BB * LL + 8) * DD];
__device__ float g_xd  [(BB * LL + 8) * DD];
__device__ float g_A2  [DD * NN];              // -exp(alpha_log) * log2(e)

__device__ __forceinline__ float ex2_approx(float x) {
    float r;
    asm("ex2.approx.ftz.f32 %0, %1;" : "=f"(r) : "f"(x));
    return r;
}

// ---------------------------------------------------------------------------
// Kernel 0: A2[d][n] = -exp(alpha_log[d][n]) * log2(e)
// ---------------------------------------------------------------------------
__global__ void a2_kernel(const float* __restrict__ alog) {
    int i = blockIdx.x * blockDim.x + threadIdx.x;
    if (i < DD * NN)
        g_A2[i] = -__expf(alog[i]) * 1.4426950408889634f;
}

// ---------------------------------------------------------------------------
// Kernel 1: proj = x @ W_in   ([1024,256] x [256,576] -> [1024,576])
// ---------------------------------------------------------------------------
__global__ void proj_kernel(const float* __restrict__ x, const float* __restrict__ W) {
    __shared__ float xs[32][33];
    __shared__ float ws[32][33];
    int row = blockIdx.y * 32 + threadIdx.y;
    int col = blockIdx.x * 32 + threadIdx.x;
    float acc = 0.f;
    for (int kt = 0; kt < DD; kt += 32) {
        xs[threadIdx.y][threadIdx.x] = x[row * DD + kt + threadIdx.x];
        ws[threadIdx.y][threadIdx.x] = W[(kt + threadIdx.y) * PW + col];
        __syncthreads();
#pragma unroll
        for (int k = 0; k < 32; k++)
            acc = fmaf(xs[threadIdx.y][k], ws[k][threadIdx.x], acc);
        __syncthreads();
    }
    g_proj[row * PW + col] = acc;
}

// ---------------------------------------------------------------------------
// Kernel 2: dt = softplus(proj[:, :64] @ W_dt + b_dt); dtx = dt*x; xd = x*delta
// ---------------------------------------------------------------------------
__global__ void dt_kernel(const float* __restrict__ x, const float* __restrict__ Wdt,
                          const float* __restrict__ bdt, const float* __restrict__ delta) {
    int r = blockIdx.x;
    int d = threadIdx.x;
    __shared__ float sp[DT];
    if (d < DT) sp[d] = g_proj[r * PW + d];
    __syncthreads();
    float acc = bdt[d];
#pragma unroll
    for (int k = 0; k < DT; k++)
        acc = fmaf(sp[k], Wdt[k * DD + d], acc);
    float dt = fmaxf(acc, 0.f) + log1pf(__expf(-fabsf(acc)));
    float xv = x[r * DD + d];
    int idx = r * DD + d;
    g_dt[idx]  = dt;
    g_dtx[idx] = dt * xv;
    g_xd[idx]  = xv * delta[d];
}

// ---------------------------------------------------------------------------
// Kernel 3: sequential scan. One warp per (b, d); lane owns 8 consecutive n.
// Explicit double-buffered 4-step batches: all operands for batch k+1 are
// issued before computing batch k (MLP ~25, covers L2 latency structurally).
// ---------------------------------------------------------------------------

// Load all operands for the 4 steps starting at LB into buffer BUF (literal).
#define LOAD_BATCH(BUF, LB) do {                                              \
    _Pragma("unroll")                                                         \
    for (int k_ = 0; k_ < 4; k_++) {                                          \
        const float* pr_ = projbase + (size_t)((LB) + k_) * PW;               \
        be0[BUF][k_] = *(const float4*)(pr_ + DT + nb);                       \
        be1[BUF][k_] = *(const float4*)(pr_ + DT + nb + 4);                   \
        ga0[BUF][k_] = *(const float4*)(pr_ + DT + DD + nb);                  \
        ga1[BUF][k_] = *(const float4*)(pr_ + DT + DD + nb + 4);              \
        dtv [BUF][k_] = dtp [((LB) + k_) * DD];                               \
        dtxv[BUF][k_] = dtxp[((LB) + k_) * DD];                               \
    }                                                                         \
    if (lane < 4) xdl[BUF] = xdp[((LB) + lane) * DD];                         \
} while (0)

// Compute the 4 steps of buffer BUF (steps LB..LB+3), reduce, store.
#define COMPUTE_BATCH(BUF, LB) do {                                           \
    float yl_[4];                                                             \
    _Pragma("unroll")                                                         \
    for (int k_ = 0; k_ < 4; k_++) {                                          \
        float dt_  = dtv [BUF][k_];                                           \
        float dtx_ = dtxv[BUF][k_];                                           \
        float be_[8] = {be0[BUF][k_].x, be0[BUF][k_].y, be0[BUF][k_].z,       \
                        be0[BUF][k_].w, be1[BUF][k_].x, be1[BUF][k_].y,       \
                        be1[BUF][k_].z, be1[BUF][k_].w};                      \
        float ga_[8] = {ga0[BUF][k_].x, ga0[BUF][k_].y, ga0[BUF][k_].z,       \
                        ga0[BUF][k_].w, ga1[BUF][k_].x, ga1[BUF][k_].y,       \
                        ga1[BUF][k_].z, ga1[BUF][k_].w};                      \
        float a0_ = 0.f, a1_ = 0.f, a2_ = 0.f, a3_ = 0.f;                     \
        _Pragma("unroll")                                                     \
        for (int j_ = 0; j_ < 8; j_++) {                                      \
            float av_ = ex2_approx(dt_ * a2v[j_]);                            \
            st[j_] = fmaf(av_, st[j_], dtx_ * be_[j_]);                       \
            float p_ = st[j_] * ga_[j_];                                      \
            if ((j_ & 3) == 0) a0_ += p_;                                     \
            else if ((j_ & 3) == 1) a1_ += p_;                                \
            else if ((j_ & 3) == 2) a2_ += p_;                                \
            else a3_ += p_;                                                   \
        }                                                                     \
        yl_[k_] = (a0_ + a1_) + (a2_ + a3_);                                  \
    }                                                                         \
    /* transposed reduction: ends with Y[lane&3] in v_ */                     \
    float s_, r0_, r1_, v_;                                                   \
    s_  = bt0 ? yl_[0] : yl_[1];                                              \
    r0_ = (bt0 ? yl_[1] : yl_[0]) + __shfl_xor_sync(fm, s_, 1);               \
    s_  = bt0 ? yl_[2] : yl_[3];                                              \
    r1_ = (bt0 ? yl_[3] : yl_[2]) + __shfl_xor_sync(fm, s_, 1);               \
    s_  = bt1 ? r0_ : r1_;                                                    \
    v_  = (bt1 ? r1_ : r0_) + __shfl_xor_sync(fm, s_, 2);                     \
    v_ += __shfl_xor_sync(fm, v_, 4);                                         \
    v_ += __shfl_xor_sync(fm, v_, 8);                                         \
    v_ += __shfl_xor_sync(fm, v_, 16);                                        \
    if (lane < 4) outp[((LB) + lane) * DD] = v_ + xdl[BUF];                   \
} while (0)

__global__ void __launch_bounds__(128) scan_kernel(float* __restrict__ out) {
    const int warp = threadIdx.x >> 5;
    const int lane = threadIdx.x & 31;
    const int b = blockIdx.x >> 6;                 // 64 CTAs per batch index
    const int d = ((blockIdx.x & 63) << 2) + warp; // 4 d per CTA
    const int nb = lane * 8;

    float a2v[8], st[8];
#pragma unroll
    for (int j = 0; j < 8; j++) {
        a2v[j] = g_A2[d * NN + nb + j];
        st[j] = 0.f;
    }

    const float* projbase = g_proj + (size_t)b * LL * PW;
    const float* dtp  = g_dt  + (size_t)b * LL * DD + d;
    const float* dtxp = g_dtx + (size_t)b * LL * DD + d;
    const float* xdp  = g_xd  + (size_t)b * LL * DD + d;
    float* outp = out + (size_t)b * LL * DD + d;

    const unsigned fm = 0xffffffffu;
    const int bt0 = lane & 1;
    const int bt1 = (lane >> 1) & 1;

    // double-buffered operand stages (register arrays, constant-indexed)
    float4 be0[2][4], be1[2][4], ga0[2][4], ga1[2][4];
    float dtv[2][4], dtxv[2][4];
    float xdl[2];

    LOAD_BATCH(0, 0);

#pragma unroll 1
    for (int lb = 0; lb < LL; lb += 8) {
        LOAD_BATCH(1, lb + 4);
        COMPUTE_BATCH(0, lb);
        LOAD_BATCH(0, lb + 8);     // over-prefetch into padded rows at the end
        COMPUTE_BATCH(1, lb + 4);
    }
}

// ---------------------------------------------------------------------------
extern "C" void kernel_launch(void* const* d_in, const int* in_sizes, int n_in,
                              void* d_out, int out_size) {
    const float* x      = (const float*)d_in[0];  // [2,512,256]
    const float* W_in   = (const float*)d_in[1];  // [256,576]
    const float* W_dt   = (const float*)d_in[2];  // [64,256]
    const float* b_dt   = (const float*)d_in[3];  // [256]
    const float* alog   = (const float*)d_in[4];  // [256,256]
    const float* delta  = (const float*)d_in[5];  // [256]
    float* out = (float*)d_out;                   // [2,512,256]

    a2_kernel<<<(DD * NN + 255) / 256, 256>>>(alog);

    dim3 pgrid(PW / 32, (BB * LL) / 32);
    dim3 pblk(32, 32);
    proj_kernel<<<pgrid, pblk>>>(x, W_in);

    dt_kernel<<<BB * LL, DD>>>(x, W_dt, b_dt, delta);

    scan_kernel<<<BB * 64, 128>>>(out);
}

// round 4
// speedup vs baseline: 2.8373x; 1.1889x over previous
#include <cuda_runtime.h>

#define BB 2
#define LL 512
#define DD 256
#define NN 256
#define DT 64
#define PW 576   // DT + 2*DD

// scratch (device globals — no allocations allowed); +8 rows padding so the
// software pipeline can over-prefetch past the end without bounds checks.
__device__ float g_proj[(BB * LL + 8) * PW];   // [row, 576] : dt_raw | beta | gamma
__device__ float g_dt  [(BB * LL + 8) * DD];
__device__ float g_dtx [(BB * LL + 8) * DD];
__device__ float g_xd  [(BB * LL + 8) * DD];
__device__ float g_A2  [DD * NN];              // -exp(alpha_log) * log2(e)

__device__ __forceinline__ float ex2_approx(float x) {
    float r;
    asm("ex2.approx.ftz.f32 %0, %1;" : "=f"(r) : "f"(x));
    return r;
}

// ---------------------------------------------------------------------------
// Kernel 0: A2[d][n] = -exp(alpha_log[d][n]) * log2(e)
// ---------------------------------------------------------------------------
__global__ void a2_kernel(const float* __restrict__ alog) {
    int i = blockIdx.x * blockDim.x + threadIdx.x;
    if (i < DD * NN)
        g_A2[i] = -__expf(alog[i]) * 1.4426950408889634f;
}

// ---------------------------------------------------------------------------
// Kernel 1: proj = x @ W_in   ([1024,256] x [256,576] -> [1024,576])
// ---------------------------------------------------------------------------
__global__ void proj_kernel(const float* __restrict__ x, const float* __restrict__ W) {
    __shared__ float xs[32][33];
    __shared__ float ws[32][33];
    int row = blockIdx.y * 32 + threadIdx.y;
    int col = blockIdx.x * 32 + threadIdx.x;
    float acc = 0.f;
    for (int kt = 0; kt < DD; kt += 32) {
        xs[threadIdx.y][threadIdx.x] = x[row * DD + kt + threadIdx.x];
        ws[threadIdx.y][threadIdx.x] = W[(kt + threadIdx.y) * PW + col];
        __syncthreads();
#pragma unroll
        for (int k = 0; k < 32; k++)
            acc = fmaf(xs[threadIdx.y][k], ws[k][threadIdx.x], acc);
        __syncthreads();
    }
    g_proj[row * PW + col] = acc;
}

// ---------------------------------------------------------------------------
// Kernel 2: dt = softplus(proj[:, :64] @ W_dt + b_dt); dtx = dt*x; xd = x*delta
// ---------------------------------------------------------------------------
__global__ void dt_kernel(const float* __restrict__ x, const float* __restrict__ Wdt,
                          const float* __restrict__ bdt, const float* __restrict__ delta) {
    int r = blockIdx.x;
    int d = threadIdx.x;
    __shared__ float sp[DT];
    if (d < DT) sp[d] = g_proj[r * PW + d];
    __syncthreads();
    float acc = bdt[d];
#pragma unroll
    for (int k = 0; k < DT; k++)
        acc = fmaf(sp[k], Wdt[k * DD + d], acc);
    float dt = fmaxf(acc, 0.f) + log1pf(__expf(-fabsf(acc)));
    float xv = x[r * DD + d];
    int idx = r * DD + d;
    g_dt[idx]  = dt;
    g_dtx[idx] = dt * xv;
    g_xd[idx]  = xv * delta[d];
}

// ---------------------------------------------------------------------------
// Kernel 3: sequential scan.
// One CTA per (b, d); 4 warps split the n-dimension (64 n each, 2 per lane).
// Warps run independently (no per-step barriers); per-warp 4-step partial y's
// go to private smem columns; a single final pass combines them.
// Double-buffered 4-step operand batches hide L2 latency structurally.
// ---------------------------------------------------------------------------

#define LOAD_BATCH(BUF, LB) do {                                              \
    _Pragma("unroll")                                                         \
    for (int k_ = 0; k_ < 4; k_++) {                                          \
        const float* pr_ = projbase + (size_t)((LB) + k_) * PW;               \
        bev[BUF][k_] = *(const float2*)(pr_ + DT + n0);                       \
        gav[BUF][k_] = *(const float2*)(pr_ + DT + DD + n0);                  \
        dtv [BUF][k_] = dtp [((LB) + k_) * DD];                               \
        dtxv[BUF][k_] = dtxp[((LB) + k_) * DD];                               \
    }                                                                         \
} while (0)

#define COMPUTE_BATCH(BUF, LB) do {                                           \
    float yl_[4];                                                             \
    _Pragma("unroll")                                                         \
    for (int k_ = 0; k_ < 4; k_++) {                                          \
        float dt_  = dtv [BUF][k_];                                           \
        float dtx_ = dtxv[BUF][k_];                                           \
        float a0_ = ex2_approx(dt_ * a2v0);                                   \
        float a1_ = ex2_approx(dt_ * a2v1);                                   \
        st0 = fmaf(a0_, st0, dtx_ * bev[BUF][k_].x);                          \
        st1 = fmaf(a1_, st1, dtx_ * bev[BUF][k_].y);                          \
        yl_[k_] = st0 * gav[BUF][k_].x + st1 * gav[BUF][k_].y;                \
    }                                                                         \
    /* transposed reduction over 32 lanes: Y[lane&3] ends in v_ */            \
    float s_, r0_, r1_, v_;                                                   \
    s_  = bt0 ? yl_[0] : yl_[1];                                              \
    r0_ = (bt0 ? yl_[1] : yl_[0]) + __shfl_xor_sync(fm, s_, 1);               \
    s_  = bt0 ? yl_[2] : yl_[3];                                              \
    r1_ = (bt0 ? yl_[3] : yl_[2]) + __shfl_xor_sync(fm, s_, 1);               \
    s_  = bt1 ? r0_ : r1_;                                                    \
    v_  = (bt1 ? r1_ : r0_) + __shfl_xor_sync(fm, s_, 2);                     \
    v_ += __shfl_xor_sync(fm, v_, 4);                                         \
    v_ += __shfl_xor_sync(fm, v_, 8);                                         \
    v_ += __shfl_xor_sync(fm, v_, 16);                                        \
    if (lane < 4) ypart[warp * LL + (LB) + lane] = v_;                        \
} while (0)

__global__ void __launch_bounds__(128) scan_kernel(float* __restrict__ out) {
    __shared__ float ypart[4 * LL];   // [warp][l]

    const int warp = threadIdx.x >> 5;
    const int lane = threadIdx.x & 31;
    const int b = blockIdx.x >> 8;         // 256 CTAs per batch index
    const int d = blockIdx.x & 255;
    const int n0 = warp * 64 + lane * 2;   // this lane's 2 n-values

    float a2v0 = g_A2[d * NN + n0];
    float a2v1 = g_A2[d * NN + n0 + 1];
    float st0 = 0.f, st1 = 0.f;

    const float* projbase = g_proj + (size_t)b * LL * PW;
    const float* dtp  = g_dt  + (size_t)b * LL * DD + d;
    const float* dtxp = g_dtx + (size_t)b * LL * DD + d;
    const float* xdp  = g_xd  + (size_t)b * LL * DD + d;
    float* outp = out + (size_t)b * LL * DD + d;

    const unsigned fm = 0xffffffffu;
    const int bt0 = lane & 1;
    const int bt1 = (lane >> 1) & 1;

    // double-buffered operand stages (constant-indexed register arrays)
    float2 bev[2][4], gav[2][4];
    float dtv[2][4], dtxv[2][4];

    LOAD_BATCH(0, 0);

#pragma unroll 1
    for (int lb = 0; lb < LL; lb += 8) {
        LOAD_BATCH(1, lb + 4);
        COMPUTE_BATCH(0, lb);
        LOAD_BATCH(0, lb + 8);     // over-prefetch into padded rows at the end
        COMPUTE_BATCH(1, lb + 4);
    }

    __syncthreads();

    // final combine: y[l] = sum of 4 warp partials + xd[l]
#pragma unroll
    for (int i = 0; i < 4; i++) {
        int l = threadIdx.x + i * 128;
        float y = ypart[l] + ypart[LL + l] + ypart[2 * LL + l] + ypart[3 * LL + l];
        outp[l * DD] = y + xdp[l * DD];
    }
}

// ---------------------------------------------------------------------------
extern "C" void kernel_launch(void* const* d_in, const int* in_sizes, int n_in,
                              void* d_out, int out_size) {
    const float* x      = (const float*)d_in[0];  // [2,512,256]
    const float* W_in   = (const float*)d_in[1];  // [256,576]
    const float* W_dt   = (const float*)d_in[2];  // [64,256]
    const float* b_dt   = (const float*)d_in[3];  // [256]
    const float* alog   = (const float*)d_in[4];  // [256,256]
    const float* delta  = (const float*)d_in[5];  // [256]
    float* out = (float*)d_out;                   // [2,512,256]

    a2_kernel<<<(DD * NN + 255) / 256, 256>>>(alog);

    dim3 pgrid(PW / 32, (BB * LL) / 32);
    dim3 pblk(32, 32);
    proj_kernel<<<pgrid, pblk>>>(x, W_in);

    dt_kernel<<<BB * LL, DD>>>(x, W_dt, b_dt, delta);

    scan_kernel<<<BB * DD, 128>>>(out);
}

// round 5
// speedup vs baseline: 3.6698x; 1.2934x over previous
#include <cuda_runtime.h>

#define BB 2
#define LL 512
#define DD 256
#define NN 256
#define DT 64
#define PW 576   // DT + 2*DD
#define NP 128   // n-pairs per row

// scratch (device globals — no allocations allowed); +16 rows padding so the
// software pipeline can over-prefetch past the end without bounds checks.
__device__ float  g_proj[(BB * LL + 16) * PW];   // [row, 576] : dt_raw | beta | gamma
__device__ float2 g_ddx [(BB * LL + 16) * DD];   // {dt, dt*x} per (row, d)
__device__ float4 g_bg  [(BB * LL + 16) * NP];   // {be0, be1, ga0, ga1} per (row, n-pair)
__device__ float  g_xd  [(BB * LL + 16) * DD];   // x * delta
__device__ float  g_A2  [DD * NN];               // -exp(alpha_log) * log2(e)

__device__ __forceinline__ float ex2_approx(float x) {
    float r;
    asm("ex2.approx.ftz.f32 %0, %1;" : "=f"(r) : "f"(x));
    return r;
}

// ---------------------------------------------------------------------------
// Kernel 0: A2[d][n] = -exp(alpha_log[d][n]) * log2(e)
// ---------------------------------------------------------------------------
__global__ void a2_kernel(const float* __restrict__ alog) {
    int i = blockIdx.x * blockDim.x + threadIdx.x;
    if (i < DD * NN)
        g_A2[i] = -__expf(alog[i]) * 1.4426950408889634f;
}

// ---------------------------------------------------------------------------
// Kernel 1: proj = x @ W_in   ([1024,256] x [256,576] -> [1024,576])
// ---------------------------------------------------------------------------
__global__ void proj_kernel(const float* __restrict__ x, const float* __restrict__ W) {
    __shared__ float xs[32][33];
    __shared__ float ws[32][33];
    int row = blockIdx.y * 32 + threadIdx.y;
    int col = blockIdx.x * 32 + threadIdx.x;
    float acc = 0.f;
    for (int kt = 0; kt < DD; kt += 32) {
        xs[threadIdx.y][threadIdx.x] = x[row * DD + kt + threadIdx.x];
        ws[threadIdx.y][threadIdx.x] = W[(kt + threadIdx.y) * PW + col];
        __syncthreads();
#pragma unroll
        for (int k = 0; k < 32; k++)
            acc = fmaf(xs[threadIdx.y][k], ws[k][threadIdx.x], acc);
        __syncthreads();
    }
    g_proj[row * PW + col] = acc;
}

// ---------------------------------------------------------------------------
// Kernel 2: dt = softplus(proj[:, :64] @ W_dt + b_dt); pack {dt, dt*x}; xd
// ---------------------------------------------------------------------------
__global__ void dt_kernel(const float* __restrict__ x, const float* __restrict__ Wdt,
                          const float* __restrict__ bdt, const float* __restrict__ delta) {
    int r = blockIdx.x;
    int d = threadIdx.x;
    __shared__ float sp[DT];
    if (d < DT) sp[d] = g_proj[r * PW + d];
    __syncthreads();
    float acc = bdt[d];
#pragma unroll
    for (int k = 0; k < DT; k++)
        acc = fmaf(sp[k], Wdt[k * DD + d], acc);
    float dt = fmaxf(acc, 0.f) + log1pf(__expf(-fabsf(acc)));
    float xv = x[r * DD + d];
    int idx = r * DD + d;
    g_ddx[idx] = make_float2(dt, dt * xv);
    g_xd[idx]  = xv * delta[d];
}

// ---------------------------------------------------------------------------
// Kernel 2b: pack beta/gamma: g_bg[r][p] = {be[2p], be[2p+1], ga[2p], ga[2p+1]}
// ---------------------------------------------------------------------------
__global__ void pack_kernel() {
    int r = blockIdx.x;
    int p = threadIdx.x;       // 0..127 n-pair
    const float* pr = g_proj + (size_t)r * PW;
    float2 be = *(const float2*)(pr + DT + 2 * p);
    float2 ga = *(const float2*)(pr + DT + DD + 2 * p);
    g_bg[(size_t)r * NP + p] = make_float4(be.x, be.y, ga.x, ga.y);
}

// ---------------------------------------------------------------------------
// Kernel 3: sequential scan.
// One CTA per (b, d); 4 warps split n (64 each, 2 per lane).
// 8-step double-buffered batches: 2 LDG per step (packed operands); the
// COMPUTE body (~350+ cyc wall) structurally covers L2 latency.
// Per-warp partial y's -> private smem columns; single final combine.
// ---------------------------------------------------------------------------

#define LOAD_BATCH(BUF, LB) do {                                              \
    _Pragma("unroll")                                                         \
    for (int k_ = 0; k_ < 8; k_++) {                                          \
        bg[BUF][k_] = bgp[(size_t)((LB) + k_) * NP];                          \
        dd[BUF][k_] = ddp[(size_t)((LB) + k_) * DD];                          \
    }                                                                         \
} while (0)

#define COMPUTE_BATCH(BUF, LB) do {                                           \
    float yl_[8];                                                             \
    _Pragma("unroll")                                                         \
    for (int k_ = 0; k_ < 8; k_++) {                                          \
        float dt_  = dd[BUF][k_].x;                                           \
        float dtx_ = dd[BUF][k_].y;                                           \
        float a0_ = ex2_approx(dt_ * a2v0);                                   \
        float a1_ = ex2_approx(dt_ * a2v1);                                   \
        st0 = fmaf(a0_, st0, dtx_ * bg[BUF][k_].x);                           \
        st1 = fmaf(a1_, st1, dtx_ * bg[BUF][k_].y);                           \
        yl_[k_] = fmaf(st0, bg[BUF][k_].z, st1 * bg[BUF][k_].w);              \
    }                                                                         \
    /* transposed reduction: Y[k] = sum over lanes of yl_[k]; ends with       \
       Y[lane&7] in v_ (9 SHFLs per 8 steps). */                              \
    float s_, r0_, r1_, r2_, r3_, q0_, q1_, v_;                               \
    s_  = bt0 ? yl_[0] : yl_[1];                                              \
    r0_ = (bt0 ? yl_[1] : yl_[0]) + __shfl_xor_sync(fm, s_, 1);               \
    s_  = bt0 ? yl_[2] : yl_[3];                                              \
    r1_ = (bt0 ? yl_[3] : yl_[2]) + __shfl_xor_sync(fm, s_, 1);               \
    s_  = bt0 ? yl_[4] : yl_[5];                                              \
    r2_ = (bt0 ? yl_[5] : yl_[4]) + __shfl_xor_sync(fm, s_, 1);               \
    s_  = bt0 ? yl_[6] : yl_[7];                                              \
    r3_ = (bt0 ? yl_[7] : yl_[6]) + __shfl_xor_sync(fm, s_, 1);               \
    s_  = bt1 ? r0_ : r1_;                                                    \
    q0_ = (bt1 ? r1_ : r0_) + __shfl_xor_sync(fm, s_, 2);                     \
    s_  = bt1 ? r2_ : r3_;                                                    \
    q1_ = (bt1 ? r3_ : r2_) + __shfl_xor_sync(fm, s_, 2);                     \
    s_  = bt2 ? q0_ : q1_;                                                    \
    v_  = (bt2 ? q1_ : q0_) + __shfl_xor_sync(fm, s_, 4);                     \
    v_ += __shfl_xor_sync(fm, v_, 8);                                         \
    v_ += __shfl_xor_sync(fm, v_, 16);                                        \
    if (lane < 8) ypart[warp * LL + (LB) + lane] = v_;                        \
} while (0)

__global__ void __launch_bounds__(128) scan_kernel(float* __restrict__ out) {
    __shared__ float ypart[4 * LL];   // [warp][l]

    const int warp = threadIdx.x >> 5;
    const int lane = threadIdx.x & 31;
    const int b = blockIdx.x >> 8;          // 256 CTAs per batch index
    const int d = blockIdx.x & 255;
    const int pidx = warp * 32 + lane;      // n-pair index (n0 = 2*pidx)

    float a2v0 = g_A2[d * NN + 2 * pidx];
    float a2v1 = g_A2[d * NN + 2 * pidx + 1];
    float st0 = 0.f, st1 = 0.f;

    const float4* bgp = g_bg  + (size_t)b * LL * NP + pidx;
    const float2* ddp = g_ddx + (size_t)b * LL * DD + d;
    const float*  xdp = g_xd  + (size_t)b * LL * DD + d;
    float* outp = out + (size_t)b * LL * DD + d;

    const unsigned fm = 0xffffffffu;
    const int bt0 = lane & 1;
    const int bt1 = (lane >> 1) & 1;
    const int bt2 = (lane >> 2) & 1;

    // double-buffered operand stages (constant-indexed register arrays)
    float4 bg[2][8];
    float2 dd[2][8];

    LOAD_BATCH(0, 0);

#pragma unroll 1
    for (int lb = 0; lb < LL; lb += 16) {
        LOAD_BATCH(1, lb + 8);
        COMPUTE_BATCH(0, lb);
        LOAD_BATCH(0, lb + 16);    // over-prefetch into padded rows at the end
        COMPUTE_BATCH(1, lb + 8);
    }

    __syncthreads();

    // final combine: y[l] = sum of 4 warp partials + xd[l]
#pragma unroll
    for (int i = 0; i < 4; i++) {
        int l = threadIdx.x + i * 128;
        float y = ypart[l] + ypart[LL + l] + ypart[2 * LL + l] + ypart[3 * LL + l];
        outp[l * DD] = y + xdp[l * DD];
    }
}

// ---------------------------------------------------------------------------
extern "C" void kernel_launch(void* const* d_in, const int* in_sizes, int n_in,
                              void* d_out, int out_size) {
    const float* x      = (const float*)d_in[0];  // [2,512,256]
    const float* W_in   = (const float*)d_in[1];  // [256,576]
    const float* W_dt   = (const float*)d_in[2];  // [64,256]
    const float* b_dt   = (const float*)d_in[3];  // [256]
    const float* alog   = (const float*)d_in[4];  // [256,256]
    const float* delta  = (const float*)d_in[5];  // [256]
    float* out = (float*)d_out;                   // [2,512,256]

    a2_kernel<<<(DD * NN + 255) / 256, 256>>>(alog);

    dim3 pgrid(PW / 32, (BB * LL) / 32);
    dim3 pblk(32, 32);
    proj_kernel<<<pgrid, pblk>>>(x, W_in);

    dt_kernel<<<BB * LL, DD>>>(x, W_dt, b_dt, delta);
    pack_kernel<<<BB * LL, NP>>>();

    scan_kernel<<<BB * DD, 128>>>(out);
}